// round 6
// baseline (speedup 1.0000x reference)
#include <cuda_runtime.h>
#include <cuda_fp16.h>
#include <cstdint>

#define B_SZ 8192
#define I_SZ 256
#define O_SZ 256
#define C_SZ 32
#define FULLMASK 0xFFFFFFFFu
#define MAX_TILES 96

// ---------------- scratch (device globals; allocation-free) ----------------
__device__ int g_perm[B_SZ];
__device__ int g_offset[C_SZ];
__device__ int g_tiles[MAX_TILES];
__device__ int g_ntiles;
__device__ int g_is64;
__device__ int g_ok64[32];
__device__ int g_h64[32 * 8 * 32];
__device__ int g_h32[32 * 8 * 32];
__device__ int g_wcur[256 * 32];
__device__ __half g_wq[C_SZ * O_SZ * I_SZ];          // [c][o][i] fp16
__device__ __half g_xp[(B_SZ + 128) * I_SZ];         // permuted x, fp16 (+pad)

// ---------------------------------------------------------------------------
// K1: blocks 0..255 conv_w; blocks 256..287 dual-dtype count + int64 vote
// ---------------------------------------------------------------------------
__global__ __launch_bounds__(256, 1)
void k1_convw_count(const float* __restrict__ weight,
                    const void* __restrict__ idx_ptr) {
    __shared__ float s[I_SZ * 33];
    __shared__ int s_h64[8][32];
    __shared__ int s_h32[8][32];
    __shared__ int s_vote[8];

    const int tid = threadIdx.x;

    if (blockIdx.x < 256) {
        const int o = blockIdx.x;
        const float* src = weight + (size_t)o * (I_SZ * C_SZ);
        for (int l = tid; l < I_SZ * C_SZ; l += 256) {
            int i = l >> 5, c = l & 31;
            s[i * 33 + c] = src[l];
        }
        __syncthreads();
        for (int u = tid; u < (I_SZ * C_SZ) / 4; u += 256) {
            int c = u >> 6, i4 = u & 63;
            union { uint2 uu; __half h[4]; } H;
#pragma unroll
            for (int j = 0; j < 4; j++)
                H.h[j] = __float2half_rn(s[(i4 * 4 + j) * 33 + c]);
            size_t off = ((size_t)c << 16) + ((size_t)o << 8) + (size_t)i4 * 4;
            *(uint2*)(g_wq + off) = H.uu;
        }
        return;
    }

    const int b2 = blockIdx.x - 256;
    const int w = tid >> 5;
    const int lane = tid & 31;
    const int e = b2 * 256 + tid;

    if (w == 0 && lane < 8) s_vote[lane] = 0;
    s_h64[w][lane] = 0;
    s_h32[w][lane] = 0;
    __syncthreads();

    const int v32 = ((const int*)idx_ptr)[e];
    const int2 v64 = ((const int2*)idx_ptr)[e];

    int ok64 = (v64.y == 0) && ((unsigned)v64.x < 32u);
    int allok = __all_sync(FULLMASK, ok64);
    if (lane == 0) s_vote[w] = allok;

    {
        int c = v64.x & 31;
        unsigned m = __match_any_sync(FULLMASK, c);
        if (lane == (__ffs(m) - 1)) s_h64[w][c] += __popc(m);
    }
    {
        int c = v32 & 31;
        unsigned m = __match_any_sync(FULLMASK, c);
        if (lane == (__ffs(m) - 1)) s_h32[w][c] += __popc(m);
    }
    __syncthreads();

    if (tid == 0) {
        int a = 1;
#pragma unroll
        for (int i = 0; i < 8; i++) a &= s_vote[i];
        g_ok64[b2] = a;
    }
    g_h64[b2 * 256 + tid] = s_h64[w][lane];
    g_h32[b2 * 256 + tid] = s_h32[w][lane];
}

// ---------------------------------------------------------------------------
// K2: 1 block: dtype resolve, prefix, per-warp cursors, tile worklist
// ---------------------------------------------------------------------------
__global__ __launch_bounds__(1024, 1)
void k2_prefix() {
    __shared__ int s_cur[256 * 32];
    __shared__ int s_tot[32];
    __shared__ int s_off[32];
    __shared__ int s_is64;

    const int tid = threadIdx.x;
    const int wid = tid >> 5;
    const int lane = tid & 31;

    if (tid < 32) {
        int v = g_ok64[tid];
        v = __all_sync(FULLMASK, v);
        if (tid == 0) { s_is64 = v; g_is64 = v; }
    }
    __syncthreads();
    const int* H = s_is64 ? g_h64 : g_h32;

    {
        const int c = wid;
        int carry = 0;
#pragma unroll
        for (int r = 0; r < 8; r++) {
            int wq = r * 32 + lane;
            int v = H[wq * 32 + c];
            int incl = v;
#pragma unroll
            for (int d = 1; d < 32; d <<= 1) {
                int u = __shfl_up_sync(FULLMASK, incl, d);
                if (lane >= d) incl += u;
            }
            s_cur[wq * 32 + c] = carry + (incl - v);
            carry += __shfl_sync(FULLMASK, incl, 31);
        }
        if (lane == 0) s_tot[c] = carry;
    }
    __syncthreads();

    if (tid < 32) {
        int v = s_tot[tid];
        int incl = v;
#pragma unroll
        for (int d = 1; d < 32; d <<= 1) {
            int u = __shfl_up_sync(FULLMASK, incl, d);
            if (lane >= d) incl += u;
        }
        int off = incl - v;
        s_off[tid] = off;
        g_offset[tid] = off;
    }
    __syncthreads();

    if (tid == 0) {
        int nt = 0;
        for (int c = 0; c < 32; c++) {
            int cnt = s_tot[c];
            for (int m = 0; m * 128 < cnt; m++) {
                int rows = min(128, cnt - m * 128);
                g_tiles[nt++] = c | (m << 8) | (rows << 16);
            }
        }
        g_ntiles = nt;
    }

#pragma unroll
    for (int i = 0; i < 8; i++) {
        int idx = tid + i * 1024;
        g_wcur[idx] = s_cur[idx] + s_off[idx & 31];
    }
}

// ---------------------------------------------------------------------------
// K3: atomic-free scatter via per-warp exclusive cursors
// ---------------------------------------------------------------------------
__global__ __launch_bounds__(256, 1)
void k3_scatter(const void* __restrict__ idx_ptr) {
    const int tid = threadIdx.x;
    const int w = tid >> 5;
    const int lane = tid & 31;
    const int b = blockIdx.x;
    const int e = b * 256 + tid;
    const int is64 = g_is64;

    int c = is64 ? (((const int2*)idx_ptr)[e].x & 31)
                 : (((const int*)idx_ptr)[e] & 31);
    unsigned m = __match_any_sync(FULLMASK, c);
    int rank = __popc(m & ((1u << lane) - 1u));
    int base = g_wcur[(b * 8 + w) * 32 + c];
    g_perm[base + rank] = e;
}

// ---------------------------------------------------------------------------
// K4: gather x rows by perm, fp32 -> fp16, write g_xp permuted (coalesced)
// 256 blocks x 256 threads x 4 tasks of 8 elements
// ---------------------------------------------------------------------------
__global__ __launch_bounds__(256, 1)
void k4_gather(const float* __restrict__ x) {
    const int t0 = blockIdx.x * 256 + threadIdx.x;
#pragma unroll
    for (int it = 0; it < 4; it++) {
        int t = t0 + it * 65536;
        int row = t >> 5, g = t & 31;
        int src_row = g_perm[row];
        const float4* src = (const float4*)(x + (size_t)src_row * I_SZ + g * 8);
        float4 v0 = src[0], v1 = src[1];
        union { uint4 u; __half2 h[4]; } P;
        P.h[0] = __float22half2_rn(make_float2(v0.x, v0.y));
        P.h[1] = __float22half2_rn(make_float2(v0.z, v0.w));
        P.h[2] = __float22half2_rn(make_float2(v1.x, v1.y));
        P.h[3] = __float22half2_rn(make_float2(v1.z, v1.w));
        *(uint4*)(g_xp + (size_t)row * I_SZ + g * 8) = P.u;
    }
}

// ---------------------------------------------------------------------------
// GEMM v2: M=128 x N=128 x K=256, cp.async 3-stage pipeline over 4 K-chunks.
// Row stride 144B (LDSM conflict-free). 2 CTAs/SM.
// ---------------------------------------------------------------------------
#define RB 144                          // bytes per 64-fp16 chunk row
#define A_CH (128 * RB)                 // 18432
#define STAGE (2 * A_CH)                // 36864
#define OFF_ROW  0
#define OFF_BIAS 512
#define OFF_PIPE 1024
#define SM_TOTAL (OFF_PIPE + 3 * STAGE) // 111616

__device__ __forceinline__ uint32_t smem_u32(const void* p) {
    uint32_t a;
    asm("{ .reg .u64 t; cvta.to.shared.u64 t, %1; cvt.u32.u64 %0, t; }"
        : "=r"(a) : "l"(p));
    return a;
}

#define CP16(dst, src) \
    asm volatile("cp.async.cg.shared.global [%0], [%1], 16;" \
                 :: "r"(dst), "l"(src) : "memory")
#define CP_COMMIT() asm volatile("cp.async.commit_group;" ::: "memory")
#define CP_WAIT(n)  asm volatile("cp.async.wait_group %0;" :: "n"(n) : "memory")

#define LDSM_X4(r0, r1, r2, r3, addr)                                       \
    asm volatile("ldmatrix.sync.aligned.m8n8.x4.shared.b16 "                \
                 "{%0,%1,%2,%3}, [%4];"                                     \
                 : "=r"(r0), "=r"(r1), "=r"(r2), "=r"(r3) : "r"(addr))

#define MMA16816(d0, d1, d2, d3, a0, a1, a2, a3, b0, b1)                    \
    asm volatile("mma.sync.aligned.m16n8k16.row.col.f32.f16.f16.f32 "       \
                 "{%0,%1,%2,%3}, {%4,%5,%6,%7}, {%8,%9}, {%0,%1,%2,%3};"    \
                 : "+f"(d0), "+f"(d1), "+f"(d2), "+f"(d3)                   \
                 : "r"(a0), "r"(a1), "r"(a2), "r"(a3), "r"(b0), "r"(b1))

__global__ __launch_bounds__(256, 2)
void gemm_mma_kernel(const float* __restrict__ bias, float* __restrict__ out) {
    extern __shared__ char smem[];
    if ((int)blockIdx.x >= g_ntiles) return;
    const int t = g_tiles[blockIdx.x];
    const int c = t & 31;
    const int m0 = ((t >> 8) & 0xFF) * 128;
    const int rows = (t >> 16) & 0xFF;
    const int base = g_offset[c] + m0;
    const int n0 = blockIdx.y * 128;

    const int tid = threadIdx.x;
    const int wid = tid >> 5;
    const int lane = tid & 31;
    const int wm = wid >> 2;
    const int wn = wid & 3;

    int* s_row = (int*)(smem + OFF_ROW);
    float* s_bias = (float*)(smem + OFF_BIAS);
    const uint32_t sb = smem_u32(smem);

    if (tid < 128) {
        s_row[tid] = g_perm[base + min(tid, rows - 1)];
        s_bias[tid] = bias[(size_t)(n0 + tid) * C_SZ + c];
    }

    // per-thread fill coordinates: 1024 16B tasks per operand per chunk
    const __half* asrc0 = g_xp + (size_t)base * I_SZ;
    const __half* wsrc0 = g_wq + ((size_t)c << 16) + (size_t)n0 * I_SZ;

    auto fill = [&](int kc, int stage) {
        const uint32_t dstA = sb + OFF_PIPE + stage * STAGE;
        const uint32_t dstW = dstA + A_CH;
        const __half* sa = asrc0 + kc * 64;
        const __half* sw = wsrc0 + kc * 64;
#pragma unroll
        for (int it = 0; it < 4; it++) {
            int task = tid + it * 256;
            int r = task >> 3, g = task & 7;
            CP16(dstA + r * RB + g * 16, sa + (size_t)r * I_SZ + g * 8);
        }
#pragma unroll
        for (int it = 0; it < 4; it++) {
            int task = tid + it * 256;
            int r = task >> 3, g = task & 7;
            CP16(dstW + r * RB + g * 16, sw + (size_t)r * I_SZ + g * 8);
        }
        CP_COMMIT();
    };

    fill(0, 0);
    fill(1, 1);
    fill(2, 2);

    float acc[4][4][4];
#pragma unroll
    for (int i = 0; i < 4; i++)
#pragma unroll
        for (int j = 0; j < 4; j++)
#pragma unroll
            for (int q = 0; q < 4; q++) acc[i][j][q] = 0.0f;

    uint32_t aoff[4], boff[2];
#pragma unroll
    for (int mt = 0; mt < 4; mt++)
        aoff[mt] = (wm * 64 + mt * 16 + (lane & 15)) * RB + (lane >> 4) * 16;
#pragma unroll
    for (int p = 0; p < 2; p++)
        boff[p] = (wn * 32 + p * 16 + (lane >> 4) * 8 + (lane & 7)) * RB +
                  ((lane >> 3) & 1) * 16;

    auto compute = [&](int stage) {
        const uint32_t ab = sb + OFF_PIPE + stage * STAGE;
        const uint32_t wb = ab + A_CH;
#pragma unroll
        for (int j = 0; j < 4; j++) {
            const uint32_t kb = j * 32;
            uint32_t a[4][4], b[2][4];
#pragma unroll
            for (int mt = 0; mt < 4; mt++)
                LDSM_X4(a[mt][0], a[mt][1], a[mt][2], a[mt][3],
                        ab + aoff[mt] + kb);
#pragma unroll
            for (int p = 0; p < 2; p++)
                LDSM_X4(b[p][0], b[p][1], b[p][2], b[p][3],
                        wb + boff[p] + kb);
#pragma unroll
            for (int mt = 0; mt < 4; mt++) {
#pragma unroll
                for (int nt = 0; nt < 4; nt++) {
                    uint32_t b0 = b[nt >> 1][(nt & 1) * 2 + 0];
                    uint32_t b1 = b[nt >> 1][(nt & 1) * 2 + 1];
                    MMA16816(acc[mt][nt][0], acc[mt][nt][1],
                             acc[mt][nt][2], acc[mt][nt][3],
                             a[mt][0], a[mt][1], a[mt][2], a[mt][3], b0, b1);
                }
            }
        }
    };

    CP_WAIT(2);          // chunk 0 resident
    __syncthreads();
    compute(0);
    __syncthreads();     // buf 0 free
    fill(3, 0);
    CP_WAIT(2);          // chunk 1 resident
    __syncthreads();
    compute(1);
    CP_WAIT(1);          // chunk 2 resident
    __syncthreads();
    compute(2);
    CP_WAIT(0);          // chunk 3 resident
    __syncthreads();
    compute(0);

    // ---- epilogue ----
    const int g = lane >> 2, tq = lane & 3;
#pragma unroll
    for (int mt = 0; mt < 4; mt++) {
        int rl = wm * 64 + mt * 16 + g;
#pragma unroll
        for (int h = 0; h < 2; h++) {
            int rr = rl + h * 8;
            if (rr < rows) {
                float* op = out + (size_t)s_row[rr] * O_SZ + n0;
#pragma unroll
                for (int nt = 0; nt < 4; nt++) {
                    int cl = wn * 32 + nt * 8 + 2 * tq;
                    float2 v;
                    v.x = acc[mt][nt][h * 2 + 0] + s_bias[cl + 0];
                    v.y = acc[mt][nt][h * 2 + 1] + s_bias[cl + 1];
                    *(float2*)(op + cl) = v;
                }
            }
        }
    }
}

// ---------------------------------------------------------------------------
// launch
// ---------------------------------------------------------------------------
extern "C" void kernel_launch(void* const* d_in, const int* in_sizes, int n_in,
                              void* d_out, int out_size) {
    const float* x      = (const float*)d_in[0];
    const void*  idx    = d_in[1];
    const float* weight = (const float*)d_in[2];
    const float* bias   = (const float*)d_in[3];
    float* out = (float*)d_out;

    cudaFuncSetAttribute(gemm_mma_kernel,
                         cudaFuncAttributeMaxDynamicSharedMemorySize, SM_TOTAL);

    k1_convw_count<<<288, 256>>>(weight, idx);
    k2_prefix<<<1, 1024>>>();
    k3_scatter<<<32, 256>>>(idx);
    k4_gather<<<256, 256>>>(x);
    dim3 grid(MAX_TILES, 2);
    gemm_mma_kernel<<<grid, 256, SM_TOTAL>>>(bias, out);
}

// round 7
// speedup vs baseline: 1.0008x; 1.0008x over previous
#include <cuda_runtime.h>
#include <cuda_fp16.h>
#include <cstdint>

#define B_SZ 8192
#define I_SZ 256
#define O_SZ 256
#define C_SZ 32
#define FULLMASK 0xFFFFFFFFu
#define MAX_TILES 96

// ---------------- scratch (device globals; allocation-free) ----------------
__device__ int g_perm[B_SZ];
__device__ int g_offset[C_SZ];
__device__ int g_tiles[MAX_TILES];
__device__ int g_ntiles;
__device__ int g_is64;
__device__ int g_ok64[32];
__device__ int g_h64[32 * 8 * 32];
__device__ int g_h32[32 * 8 * 32];
__device__ int g_wcur[256 * 32];
__device__ __half g_wq[C_SZ * O_SZ * I_SZ];      // [c][o][i] fp16
__device__ __half g_xp[(B_SZ + 128) * I_SZ];     // permuted x fp16 (+pad rows)

// ---------------------------------------------------------------------------
// kA: count — 32 blocks x 256. Dual-dtype warp-private hists + int64 vote.
// ---------------------------------------------------------------------------
__global__ __launch_bounds__(256, 1)
void kA_count(const void* __restrict__ idx_ptr) {
    __shared__ int s_h64[8][32];
    __shared__ int s_h32[8][32];
    __shared__ int s_vote[8];

    const int tid = threadIdx.x;
    const int b = blockIdx.x;
    const int w = tid >> 5;
    const int lane = tid & 31;
    const int e = b * 256 + tid;

    if (w == 0 && lane < 8) s_vote[lane] = 0;
    s_h64[w][lane] = 0;
    s_h32[w][lane] = 0;
    __syncthreads();

    const int v32 = ((const int*)idx_ptr)[e];
    const int2 v64 = ((const int2*)idx_ptr)[e];

    int ok64 = (v64.y == 0) && ((unsigned)v64.x < 32u);
    int allok = __all_sync(FULLMASK, ok64);
    if (lane == 0) s_vote[w] = allok;

    {
        int c = v64.x & 31;
        unsigned m = __match_any_sync(FULLMASK, c);
        if (lane == (__ffs(m) - 1)) s_h64[w][c] += __popc(m);
    }
    {
        int c = v32 & 31;
        unsigned m = __match_any_sync(FULLMASK, c);
        if (lane == (__ffs(m) - 1)) s_h32[w][c] += __popc(m);
    }
    __syncthreads();

    if (tid == 0) {
        int a = 1;
#pragma unroll
        for (int i = 0; i < 8; i++) a &= s_vote[i];
        g_ok64[b] = a;
    }
    g_h64[b * 256 + tid] = s_h64[w][lane];
    g_h32[b * 256 + tid] = s_h32[w][lane];
}

// ---------------------------------------------------------------------------
// K2: 1 block: dtype resolve, prefix, per-warp cursors, tile worklist
// ---------------------------------------------------------------------------
__global__ __launch_bounds__(1024, 1)
void k2_prefix() {
    __shared__ int s_cur[256 * 32];
    __shared__ int s_tot[32];
    __shared__ int s_off[32];
    __shared__ int s_is64;

    const int tid = threadIdx.x;
    const int wid = tid >> 5;
    const int lane = tid & 31;

    if (tid < 32) {
        int v = g_ok64[tid];
        v = __all_sync(FULLMASK, v);
        if (tid == 0) { s_is64 = v; g_is64 = v; }
    }
    __syncthreads();
    const int* H = s_is64 ? g_h64 : g_h32;

    {
        const int c = wid;
        int carry = 0;
#pragma unroll
        for (int r = 0; r < 8; r++) {
            int wq = r * 32 + lane;
            int v = H[wq * 32 + c];
            int incl = v;
#pragma unroll
            for (int d = 1; d < 32; d <<= 1) {
                int u = __shfl_up_sync(FULLMASK, incl, d);
                if (lane >= d) incl += u;
            }
            s_cur[wq * 32 + c] = carry + (incl - v);
            carry += __shfl_sync(FULLMASK, incl, 31);
        }
        if (lane == 0) s_tot[c] = carry;
    }
    __syncthreads();

    if (tid < 32) {
        int v = s_tot[tid];
        int incl = v;
#pragma unroll
        for (int d = 1; d < 32; d <<= 1) {
            int u = __shfl_up_sync(FULLMASK, incl, d);
            if (lane >= d) incl += u;
        }
        int off = incl - v;
        s_off[tid] = off;
        g_offset[tid] = off;
    }
    __syncthreads();

    if (tid == 0) {
        int nt = 0;
        for (int c = 0; c < 32; c++) {
            int cnt = s_tot[c];
            for (int m = 0; m * 128 < cnt; m++) {
                int rows = min(128, cnt - m * 128);
                g_tiles[nt++] = c | (m << 8) | (rows << 16);
            }
        }
        g_ntiles = nt;
    }

#pragma unroll
    for (int i = 0; i < 8; i++) {
        int idx = tid + i * 1024;
        g_wcur[idx] = s_cur[idx] + s_off[idx & 31];
    }
}

// ---------------------------------------------------------------------------
// K3: atomic-free scatter via per-warp exclusive cursors
// ---------------------------------------------------------------------------
__global__ __launch_bounds__(256, 1)
void k3_scatter(const void* __restrict__ idx_ptr) {
    const int tid = threadIdx.x;
    const int w = tid >> 5;
    const int lane = tid & 31;
    const int b = blockIdx.x;
    const int e = b * 256 + tid;
    const int is64 = g_is64;

    int c = is64 ? (((const int2*)idx_ptr)[e].x & 31)
                 : (((const int*)idx_ptr)[e] & 31);
    unsigned m = __match_any_sync(FULLMASK, c);
    int rank = __popc(m & ((1u << lane) - 1u));
    int base = g_wcur[(b * 8 + w) * 32 + c];
    g_perm[base + rank] = e;
}

// ---------------------------------------------------------------------------
// kB: blocks 0..1023  -> gather x rows by perm -> g_xp fp16 (1 task/thread)
//     blocks 1024..1279 -> conv_w (weight [O][I][C] f32 -> [C][O][I] f16)
// ---------------------------------------------------------------------------
__global__ __launch_bounds__(256, 1)
void kB_gather_convw(const float* __restrict__ x,
                     const float* __restrict__ weight) {
    __shared__ __half sh[I_SZ * 33];     // 16896 B, conv path only

    if (blockIdx.x < 1024) {
        const int t = blockIdx.x * 256 + threadIdx.x;   // 262144 tasks
        const int row = t >> 5, g = t & 31;
        const int src_row = g_perm[row];
        const float4* src = (const float4*)(x + (size_t)src_row * I_SZ + g * 8);
        float4 v0 = src[0], v1 = src[1];
        union { uint4 u; __half2 h[4]; } P;
        P.h[0] = __float22half2_rn(make_float2(v0.x, v0.y));
        P.h[1] = __float22half2_rn(make_float2(v0.z, v0.w));
        P.h[2] = __float22half2_rn(make_float2(v1.x, v1.y));
        P.h[3] = __float22half2_rn(make_float2(v1.z, v1.w));
        *(uint4*)(g_xp + (size_t)row * I_SZ + g * 8) = P.u;
        return;
    }

    // ---------------- conv_w ----------------
    const int o = blockIdx.x - 1024;
    const int tid = threadIdx.x;
    const float* src = weight + (size_t)o * (I_SZ * C_SZ);

    for (int l = tid; l < I_SZ * C_SZ; l += 256) {
        int i = l >> 5, c = l & 31;
        sh[i * 33 + c] = __float2half_rn(src[l]);
    }
    __syncthreads();

    for (int u = tid; u < (I_SZ * C_SZ) / 4; u += 256) {
        int c = u >> 6, i4 = u & 63;
        union { uint2 uu; __half h[4]; } H;
#pragma unroll
        for (int j = 0; j < 4; j++)
            H.h[j] = sh[(i4 * 4 + j) * 33 + c];
        size_t off = ((size_t)c << 16) + ((size_t)o << 8) + (size_t)i4 * 4;
        *(uint2*)(g_wq + off) = H.uu;
    }
}

// ---------------------------------------------------------------------------
// GEMM: M=128 x N=128 x K=256, cp.async 3-stage pipeline over 4 K-chunks.
// ---------------------------------------------------------------------------
#define RB 144
#define A_CH (128 * RB)
#define STAGE (2 * A_CH)
#define OFF_ROW  0
#define OFF_BIAS 512
#define OFF_PIPE 1024
#define SM_TOTAL (OFF_PIPE + 3 * STAGE)   // 111616

__device__ __forceinline__ uint32_t smem_u32(const void* p) {
    uint32_t a;
    asm("{ .reg .u64 t; cvta.to.shared.u64 t, %1; cvt.u32.u64 %0, t; }"
        : "=r"(a) : "l"(p));
    return a;
}

#define CP16(dst, src) \
    asm volatile("cp.async.cg.shared.global [%0], [%1], 16;" \
                 :: "r"(dst), "l"(src) : "memory")
#define CP_COMMIT() asm volatile("cp.async.commit_group;" ::: "memory")
#define CP_WAIT(n)  asm volatile("cp.async.wait_group %0;" :: "n"(n) : "memory")

#define LDSM_X4(r0, r1, r2, r3, addr)                                       \
    asm volatile("ldmatrix.sync.aligned.m8n8.x4.shared.b16 "                \
                 "{%0,%1,%2,%3}, [%4];"                                     \
                 : "=r"(r0), "=r"(r1), "=r"(r2), "=r"(r3) : "r"(addr))

#define MMA16816(d0, d1, d2, d3, a0, a1, a2, a3, b0, b1)                    \
    asm volatile("mma.sync.aligned.m16n8k16.row.col.f32.f16.f16.f32 "       \
                 "{%0,%1,%2,%3}, {%4,%5,%6,%7}, {%8,%9}, {%0,%1,%2,%3};"    \
                 : "+f"(d0), "+f"(d1), "+f"(d2), "+f"(d3)                   \
                 : "r"(a0), "r"(a1), "r"(a2), "r"(a3), "r"(b0), "r"(b1))

__global__ __launch_bounds__(256, 2)
void gemm_mma_kernel(const float* __restrict__ bias, float* __restrict__ out) {
    extern __shared__ char smem[];
    if ((int)blockIdx.x >= g_ntiles) return;
    const int t = g_tiles[blockIdx.x];
    const int c = t & 31;
    const int m0 = ((t >> 8) & 0xFF) * 128;
    const int rows = (t >> 16) & 0xFF;
    const int base = g_offset[c] + m0;
    const int n0 = blockIdx.y * 128;

    const int tid = threadIdx.x;
    const int wid = tid >> 5;
    const int lane = tid & 31;
    const int wm = wid >> 2;
    const int wn = wid & 3;

    int* s_row = (int*)(smem + OFF_ROW);
    float* s_bias = (float*)(smem + OFF_BIAS);
    const uint32_t sb = smem_u32(smem);

    if (tid < 128) {
        s_row[tid] = g_perm[base + min(tid, rows - 1)];
        s_bias[tid] = bias[(size_t)(n0 + tid) * C_SZ + c];
    }

    const __half* asrc0 = g_xp + (size_t)base * I_SZ;
    const __half* wsrc0 = g_wq + ((size_t)c << 16) + (size_t)n0 * I_SZ;

    auto fill = [&](int kc, int stage) {
        const uint32_t dstA = sb + OFF_PIPE + stage * STAGE;
        const uint32_t dstW = dstA + A_CH;
        const __half* sa = asrc0 + kc * 64;
        const __half* sw = wsrc0 + kc * 64;
#pragma unroll
        for (int it = 0; it < 4; it++) {
            int task = tid + it * 256;
            int r = task >> 3, g = task & 7;
            CP16(dstA + r * RB + g * 16, sa + (size_t)r * I_SZ + g * 8);
        }
#pragma unroll
        for (int it = 0; it < 4; it++) {
            int task = tid + it * 256;
            int r = task >> 3, g = task & 7;
            CP16(dstW + r * RB + g * 16, sw + (size_t)r * I_SZ + g * 8);
        }
        CP_COMMIT();
    };

    fill(0, 0);
    fill(1, 1);
    fill(2, 2);

    float acc[4][4][4];
#pragma unroll
    for (int i = 0; i < 4; i++)
#pragma unroll
        for (int j = 0; j < 4; j++)
#pragma unroll
            for (int q = 0; q < 4; q++) acc[i][j][q] = 0.0f;

    uint32_t aoff[4], boff[2];
#pragma unroll
    for (int mt = 0; mt < 4; mt++)
        aoff[mt] = (wm * 64 + mt * 16 + (lane & 15)) * RB + (lane >> 4) * 16;
#pragma unroll
    for (int p = 0; p < 2; p++)
        boff[p] = (wn * 32 + p * 16 + (lane >> 4) * 8 + (lane & 7)) * RB +
                  ((lane >> 3) & 1) * 16;

    auto compute = [&](int stage) {
        const uint32_t ab = sb + OFF_PIPE + stage * STAGE;
        const uint32_t wb = ab + A_CH;
#pragma unroll
        for (int j = 0; j < 4; j++) {
            const uint32_t kb = j * 32;
            uint32_t a[4][4], b[2][4];
#pragma unroll
            for (int mt = 0; mt < 4; mt++)
                LDSM_X4(a[mt][0], a[mt][1], a[mt][2], a[mt][3],
                        ab + aoff[mt] + kb);
#pragma unroll
            for (int p = 0; p < 2; p++)
                LDSM_X4(b[p][0], b[p][1], b[p][2], b[p][3],
                        wb + boff[p] + kb);
#pragma unroll
            for (int mt = 0; mt < 4; mt++) {
#pragma unroll
                for (int nt = 0; nt < 4; nt++) {
                    uint32_t b0 = b[nt >> 1][(nt & 1) * 2 + 0];
                    uint32_t b1 = b[nt >> 1][(nt & 1) * 2 + 1];
                    MMA16816(acc[mt][nt][0], acc[mt][nt][1],
                             acc[mt][nt][2], acc[mt][nt][3],
                             a[mt][0], a[mt][1], a[mt][2], a[mt][3], b0, b1);
                }
            }
        }
    };

    CP_WAIT(2);
    __syncthreads();
    compute(0);
    __syncthreads();
    fill(3, 0);
    CP_WAIT(2);
    __syncthreads();
    compute(1);
    CP_WAIT(1);
    __syncthreads();
    compute(2);
    CP_WAIT(0);
    __syncthreads();
    compute(0);

    // ---- epilogue ----
    const int g = lane >> 2, tq = lane & 3;
#pragma unroll
    for (int mt = 0; mt < 4; mt++) {
        int rl = wm * 64 + mt * 16 + g;
#pragma unroll
        for (int h = 0; h < 2; h++) {
            int rr = rl + h * 8;
            if (rr < rows) {
                float* op = out + (size_t)s_row[rr] * O_SZ + n0;
#pragma unroll
                for (int nt = 0; nt < 4; nt++) {
                    int cl = wn * 32 + nt * 8 + 2 * tq;
                    float2 v;
                    v.x = acc[mt][nt][h * 2 + 0] + s_bias[cl + 0];
                    v.y = acc[mt][nt][h * 2 + 1] + s_bias[cl + 1];
                    *(float2*)(op + cl) = v;
                }
            }
        }
    }
}

// ---------------------------------------------------------------------------
// launch
// ---------------------------------------------------------------------------
extern "C" void kernel_launch(void* const* d_in, const int* in_sizes, int n_in,
                              void* d_out, int out_size) {
    const float* x      = (const float*)d_in[0];
    const void*  idx    = d_in[1];
    const float* weight = (const float*)d_in[2];
    const float* bias   = (const float*)d_in[3];
    float* out = (float*)d_out;

    cudaFuncSetAttribute(gemm_mma_kernel,
                         cudaFuncAttributeMaxDynamicSharedMemorySize, SM_TOTAL);

    kA_count<<<32, 256>>>(idx);
    k2_prefix<<<1, 1024>>>();
    k3_scatter<<<32, 256>>>(idx);
    kB_gather_convw<<<1280, 256>>>(x, weight);
    dim3 grid(MAX_TILES, 2);
    gemm_mma_kernel<<<grid, 256, SM_TOTAL>>>(bias, out);
}